// round 12
// baseline (speedup 1.0000x reference)
#include <cuda_runtime.h>
#include <cstdint>
#include <math.h>

#define NBIN 65536
#define MAXB 16
#define NMAX 262144
#define ZN (MAXB * NBIN / 4)

#define SEL_TPB 1024
#define SEL_NCTA 296

#define GE_TPB 512
#define GE_NCTA 296                  // 2 CTAs per SM
#define TILE_P 32
#define ROWB 1040                    // 260 words: conflict-free x LDS.128
#define XBUF (TILE_P * ROWB)         // 33280
#define SLOT 48                      // 12 words: phase-distinct fold STS.128
#define SW_OFF (2 * XBUF)            // 66560
#define SIDX_OFF (SW_OFF + 24576)    // 91136
#define SB_OFF (SIDX_OFF + 256)      // 91392
#define MBAR_OFF (SB_OFF + 96)       // 91488
#define SMEM_TOT (MBAR_OFF + 32)     // 91520 -> 2 CTAs/SM

// ---- device scratch (zero-init; every run restores zero state) ----
__device__ unsigned g_hist1[MAXB * NBIN];
__device__ unsigned g_hist2[MAXB * NBIN];
__device__ unsigned g_chunk1[MAXB * 256];
__device__ unsigned g_chunk2[MAXB * 256];
__device__ unsigned g_bucket1[MAXB];
__device__ unsigned g_rank1[MAXB];
__device__ unsigned g_kthkey[MAXB];
__device__ int g_list[NMAX];
__device__ int g_cnt;
__device__ unsigned g_bar[8];        // monotonic barrier counters (never reset)

__device__ __forceinline__ unsigned f2key(float s) {
    unsigned u = __float_as_uint(s);
    return (u & 0x80000000u) ? ~u : (u | 0x80000000u);
}
__device__ __forceinline__ unsigned long long ffma2(
    unsigned long long a, unsigned long long b, unsigned long long c) {
    unsigned long long d;
    asm("fma.rn.f32x2 %0, %1, %2, %3;" : "=l"(d) : "l"(a), "l"(b), "l"(c));
    return d;
}
__device__ __forceinline__ unsigned long long addf2(
    unsigned long long a, unsigned long long b) {
    unsigned long long d;
    asm("add.rn.f32x2 %0, %1, %2;" : "=l"(d) : "l"(a), "l"(b));
    return d;
}
__device__ __forceinline__ unsigned long long pack2(float x) {
    unsigned long long d;
    asm("mov.b64 %0, {%1, %1};" : "=l"(d) : "f"(x));
    return d;
}
__device__ __forceinline__ void unpack2(unsigned long long v, float& lo, float& hi) {
    asm("mov.b64 {%0, %1}, %2;" : "=f"(lo), "=f"(hi) : "l"(v));
}
__device__ __forceinline__ float getc(const float4& v, int s) {
    return (s == 0) ? v.x : (s == 1) ? v.y : (s == 2) ? v.z : v.w;
}
__device__ __forceinline__ uint32_t s2u(const void* p) {
    uint32_t a;
    asm("{ .reg .u64 t; cvta.to.shared.u64 t, %1; cvt.u32.u64 %0, t; }"
        : "=r"(a) : "l"(p));
    return a;
}
__device__ __forceinline__ void mbar_init(uint32_t mbar, uint32_t cnt) {
    asm volatile("mbarrier.init.shared.b64 [%0], %1;" :: "r"(mbar), "r"(cnt) : "memory");
}
__device__ __forceinline__ void mbar_expect(uint32_t mbar, uint32_t bytes) {
    asm volatile("mbarrier.arrive.expect_tx.shared.b64 _, [%0], %1;"
                 :: "r"(mbar), "r"(bytes) : "memory");
}
__device__ __forceinline__ void mbar_wait(uint32_t mbar, uint32_t parity) {
    asm volatile(
        "{\n\t.reg .pred P;\n"
        "WL_%=:\n\t"
        "mbarrier.try_wait.parity.acquire.cta.shared::cta.b64 P, [%0], %1, 0x989680;\n\t"
        "@P bra.uni WD_%=;\n\t"
        "bra.uni WL_%=;\n"
        "WD_%=:\n\t}"
        :: "r"(mbar), "r"(parity) : "memory");
}
__device__ __forceinline__ void bulk_copy(uint32_t dst, const void* src,
                                          uint32_t bytes, uint32_t mbar) {
    asm volatile(
        "cp.async.bulk.shared::cluster.global.mbarrier::complete_tx::bytes "
        "[%0], [%1], %2, [%3];"
        :: "r"(dst), "l"(src), "r"(bytes), "r"(mbar) : "memory");
}

// Reset-free grid barrier (SEL_NCTA CTAs, all co-resident).
__device__ __forceinline__ void gbar(int i) {
    __syncthreads();
    if (threadIdx.x == 0) {
        __threadfence();
        unsigned old = atomicAdd(&g_bar[i], 1u);
        unsigned target = old - (old % SEL_NCTA) + SEL_NCTA;
        unsigned cur;
        do {
            asm volatile("ld.acquire.gpu.global.u32 %0, [%1];"
                         : "=r"(cur) : "l"(&g_bar[i]) : "memory");
        } while ((int)(cur - target) < 0);
    }
    __syncthreads();
}

// CTA b handles batch b; threads 0..255 active; two shfl suffix scans.
__device__ void scan_phase(int level, int b, unsigned target,
                           unsigned* wsum, int* s_sel, unsigned* s_rem) {
    const unsigned* h  = (level == 1 ? g_hist1  : g_hist2)  + (size_t)b * NBIN;
    const unsigned* ch = (level == 1 ? g_chunk1 : g_chunk2) + (size_t)b * 256;

    int t = threadIdx.x, lane = t & 31, w = t >> 5;
    unsigned v = 0, x = 0;

    if (t < 256) {
        v = ch[t];
        x = v;
#pragma unroll
        for (int off = 1; off < 32; off <<= 1) {
            unsigned nv = __shfl_down_sync(0xffffffffu, x, off);
            if (lane + off < 32) x += nv;
        }
        if (lane == 0) wsum[w] = x;
    }
    __syncthreads();
    if (t < 256) {
        unsigned add = 0;
        for (int w2 = w + 1; w2 < 8; w2++) add += wsum[w2];
        unsigned s = x + add;
        if (s >= target && s - v < target) { *s_sel = t; *s_rem = target - (s - v); }
    }
    __syncthreads();
    int sel = *s_sel;
    unsigned rem = *s_rem;
    __syncthreads();

    if (t < 256) {
        v = h[sel * 256 + t];
        x = v;
#pragma unroll
        for (int off = 1; off < 32; off <<= 1) {
            unsigned nv = __shfl_down_sync(0xffffffffu, x, off);
            if (lane + off < 32) x += nv;
        }
        if (lane == 0) wsum[w] = x;
    }
    __syncthreads();
    if (t < 256) {
        unsigned add = 0;
        for (int w2 = w + 1; w2 < 8; w2++) add += wsum[w2];
        unsigned s = x + add;
        if (s >= rem && s - v < rem) {
            unsigned bin = (unsigned)(sel * 256 + t);
            if (level == 1) {
                g_bucket1[b] = bin;
                g_rank1[b] = rem - (s - v);
            } else {
                g_kthkey[b] = (g_bucket1[b] << 16) | bin;
            }
        }
    }
}

// Fused selection: hist1 -> scan1 -> hist2 -> scan2 -> compact/fill.
__global__ void __launch_bounds__(SEL_TPB, 2) sel_kernel(
    const float* __restrict__ scores,
    const int* __restrict__ bids,
    const float* __restrict__ b_cls,
    const int* __restrict__ nb_ptr,
    const int* __restrict__ k_ptr,
    float4* __restrict__ out4, int N) {
    __shared__ unsigned wsum[8];
    __shared__ int s_sel;
    __shared__ unsigned s_rem;
    __shared__ float sbq[24];
    __shared__ unsigned skey[MAXB];
    __shared__ int warp_cnt[32];
    __shared__ int warp_off[32];
    __shared__ int cta_base;

    int t = threadIdx.x;
    int bid = blockIdx.x;
    int gid = bid * SEL_TPB + t;

    int B = nb_ptr ? *nb_ptr : 8;
    if (B < 1 || B > MAXB) B = 8;
    unsigned K = (unsigned)(k_ptr ? *k_ptr : 8192);

    // P1: hist1 + chunk1
    if (gid < N) {
        unsigned b = (unsigned)bids[gid];
        if (b < (unsigned)MAXB) {
            unsigned key = f2key(scores[gid]);
            atomicAdd(&g_hist1[b * NBIN + (key >> 16)], 1u);
            atomicAdd(&g_chunk1[b * 256 + (key >> 24)], 1u);
        }
    }
    gbar(0);

    // P2: scan level 1
    if (bid < B) scan_phase(1, bid, K, wsum, &s_sel, &s_rem);
    gbar(1);

    // P3: hist2 + chunk2; zero level-1 state
    if (gid < ZN) reinterpret_cast<uint4*>(g_hist1)[gid] = make_uint4(0u, 0u, 0u, 0u);
    if (gid < MAXB * 256) g_chunk1[gid] = 0u;
    if (gid < N) {
        unsigned b = (unsigned)bids[gid];
        if (b < (unsigned)MAXB) {
            unsigned key = f2key(scores[gid]);
            if ((key >> 16) == g_bucket1[b]) {
                atomicAdd(&g_hist2[b * NBIN + (key & 0xFFFFu)], 1u);
                atomicAdd(&g_chunk2[b * 256 + ((key >> 8) & 0xFFu)], 1u);
            }
        }
    }
    gbar(2);

    // P4: scan level 2 + reset g_cnt
    if (bid == 0 && t == 0) g_cnt = 0;
    if (bid < B) scan_phase(2, bid, g_rank1[bid], wsum, &s_sel, &s_rem);
    gbar(3);

    // P5: compact (CTA-aggregated g_cnt atomic) + fill; zero level-2 state
    if (t < MAXB) skey[t] = g_kthkey[t];
    if (t < 24) sbq[t] = (t < 6) ? 1.0f : b_cls[t - 6];
    __syncthreads();

    if (gid < ZN) reinterpret_cast<uint4*>(g_hist2)[gid] = make_uint4(0u, 0u, 0u, 0u);
    if (gid < MAXB * 256) g_chunk2[gid] = 0u;

    bool keep = false;
    if (gid < N) {
        unsigned b = (unsigned)bids[gid];
        unsigned key = f2key(scores[gid]);
        keep = (b < (unsigned)MAXB) && (key >= skey[b]);
        if (!keep) {
            float4* o = out4 + (size_t)gid * 6;
            o[0] = make_float4(1.f, 1.f, 1.f, 1.f);
            o[1] = make_float4(1.f, 1.f, sbq[6], sbq[7]);
            o[2] = make_float4(sbq[8], sbq[9], sbq[10], sbq[11]);
            o[3] = make_float4(sbq[12], sbq[13], sbq[14], sbq[15]);
            o[4] = make_float4(sbq[16], sbq[17], sbq[18], sbq[19]);
            o[5] = make_float4(sbq[20], sbq[21], sbq[22], sbq[23]);
        }
    }
    int lane = t & 31, w = t >> 5;
    unsigned bal = __ballot_sync(0xffffffffu, keep);
    int nk = __popc(bal);
    if (lane == 0) warp_cnt[w] = nk;
    __syncthreads();
    if (t < 32) {
        int v = warp_cnt[t];
        int inc = v;
#pragma unroll
        for (int o = 1; o < 32; o <<= 1) {
            int n = __shfl_up_sync(0xffffffffu, inc, o);
            if (t >= o) inc += n;
        }
        warp_off[t] = inc - v;
        if (t == 31) cta_base = atomicAdd(&g_cnt, inc);
    }
    __syncthreads();
    if (keep)
        g_list[cta_base + warp_off[w] + __popc(bal & ((1u << lane) - 1u))] = gid;
}

// Staged GEMV: tile=32 pts, 512 thr = 8 k-slices(32k) x 2 output-halves,
// lane owns 1 pt. 2 CTAs/SM (8 warps/SMSP). Double-buffered cp.async.bulk.
__global__ void __launch_bounds__(GE_TPB, 2) gemv_kernel(
    const float* __restrict__ feats,
    const float* __restrict__ w_reg,
    const float* __restrict__ w_cls,
    const float* __restrict__ b_cls,
    const float* __restrict__ scale,
    float* __restrict__ out) {
    extern __shared__ char smem[];
    float* sw = (float*)(smem + SW_OFF);    // [256][24]
    int* sidx = (int*)(smem + SIDX_OFF);    // [2][32]
    float* sb = (float*)(smem + SB_OFF);
    uint32_t mb0 = s2u(smem + MBAR_OFF);
    uint32_t mb1 = mb0 + 8;

    int t = threadIdx.x;
    int l = t & 31, wid = t >> 5;
    int q = wid & 7;                 // k-slice [32q, 32q+32)
    int jh = wid >> 3;               // output half: floats [12jh, 12jh+12)

    if (t < 24) sb[t] = (t < 6) ? 1.0f : b_cls[t - 6];
    for (int i = t; i < 6144; i += GE_TPB) {
        int k = i / 24, j = i % 24;
        sw[i] = (j < 6) ? w_reg[k * 6 + j] : w_cls[k * 18 + (j - 6)];
    }
    if (t < 2) mbar_init(t == 0 ? mb0 : mb1, 1);
    float sc = scale[0];
    int T = g_cnt;
    int ntiles = (T + TILE_P - 1) / TILE_P;
    __syncthreads();

    int tile = blockIdx.x;
    int ph0 = 0, ph1 = 0;

    if (tile < ntiles) {
        int nv = min(TILE_P, T - tile * TILE_P);
        if (t < TILE_P) sidx[t] = (t < nv) ? g_list[tile * TILE_P + t] : 0;
        if (t == 0) mbar_expect(mb0, (unsigned)nv << 10);
    }
    __syncthreads();
    if (tile < ntiles && t < min(TILE_P, T - tile * TILE_P))
        bulk_copy(s2u(smem) + t * ROWB, feats + (size_t)sidx[t] * 256, 1024, mb0);

    // per-(q,jh) weight base: k-stride = 96B = 6 ulonglong2
    const ulonglong2* wp = (const ulonglong2*)(sw + q * 768 + jh * 12);

    int b = 0;
    for (; tile < ntiles; tile += GE_NCTA, b ^= 1) {
        int nv = min(TILE_P, T - tile * TILE_P);
        int nxt = tile + GE_NCTA;
        int bn = b ^ 1;
        uint32_t mbn = bn ? mb1 : mb0;

        if (nxt < ntiles) {
            int nv2 = min(TILE_P, T - nxt * TILE_P);
            if (t < TILE_P) sidx[bn * TILE_P + t] = (t < nv2) ? g_list[nxt * TILE_P + t] : 0;
            if (t == 0) mbar_expect(mbn, (unsigned)nv2 << 10);
        }
        __syncthreads();
        if (nxt < ntiles) {
            int nv2 = min(TILE_P, T - nxt * TILE_P);
            if (t < nv2)
                bulk_copy(s2u(smem) + bn * XBUF + t * ROWB,
                          feats + (size_t)sidx[bn * TILE_P + t] * 256, 1024, mbn);
        }

        if (b == 0) { mbar_wait(mb0, ph0); ph0 ^= 1; }
        else        { mbar_wait(mb1, ph1); ph1 ^= 1; }

        // compute: pt l, k in [32q,32q+32), output pairs [6jh,6jh+6)
        const float4* x0 = (const float4*)(smem + b * XBUF + l * ROWB) + q * 8;
        unsigned long long acc0[6];
#pragma unroll
        for (int j = 0; j < 6; j++) acc0[j] = 0ull;

        ulonglong2 wA0 = wp[0], wA1 = wp[1], wA2 = wp[2];  // k = 32q
        float4 a0 = x0[0];
#pragma unroll
        for (int c4 = 0; c4 < 8; c4++) {
            float4 n0;
            if (c4 < 7) n0 = x0[c4 + 1];
#pragma unroll
            for (int s = 0; s < 4; s++) {
                ulonglong2 w0 = wA0, w1 = wA1, w2 = wA2;
                int kn = c4 * 4 + s + 1;
                if (kn < 32) {
                    const ulonglong2* wn = wp + kn * 6;
                    wA0 = wn[0]; wA1 = wn[1]; wA2 = wn[2];
                }
                unsigned long long xx0 = pack2(getc(a0, s));
                acc0[0] = ffma2(xx0, w0.x, acc0[0]);
                acc0[1] = ffma2(xx0, w0.y, acc0[1]);
                acc0[2] = ffma2(xx0, w1.x, acc0[2]);
                acc0[3] = ffma2(xx0, w1.y, acc0[3]);
                acc0[4] = ffma2(xx0, w2.x, acc0[4]);
                acc0[5] = ffma2(xx0, w2.y, acc0[5]);
            }
            a0 = n0;
        }
        __syncthreads();  // all x reads done; buffer b becomes scratch

        // single-phase fold store: slot (wid*32+l), 3 x STS.128
        // 512 slots x 48 B = 24576 <= XBUF; 12-word stride: phase-distinct
        char* scratch = smem + b * XBUF;
        {
            ulonglong2* dst = (ulonglong2*)(scratch + (wid * 32 + l) * SLOT);
            dst[0] = make_ulonglong2(acc0[0], acc0[1]);
            dst[1] = make_ulonglong2(acc0[2], acc0[3]);
            dst[2] = make_ulonglong2(acc0[4], acc0[5]);
        }
        __syncthreads();

        // epilogue: fold 8 q-partials per (point, output-pair); 384 tasks
        if (t < 384) {
            int pt = t & 31, jj = t >> 5;       // jj in [0,12)
            int jh2 = jj / 6, j6 = jj % 6;
            unsigned long long sum = 0ull;
#pragma unroll
            for (int q2 = 0; q2 < 8; q2++) {
                unsigned long long pv = *(const unsigned long long*)(
                    scratch + ((jh2 * 8 + q2) * 32 + pt) * SLOT + j6 * 8);
                sum = addf2(sum, pv);
            }
            if (pt < nv) {
                float lo, hi;
                unpack2(sum, lo, hi);
                int col = jh2 * 12 + j6 * 2;
                float2 o;
                if (col < 6) { o.x = __expf(sc * lo); o.y = __expf(sc * hi); }
                else         { o.x = lo + sb[col];    o.y = hi + sb[col + 1]; }
                *(float2*)(out + (size_t)sidx[b * TILE_P + pt] * 24 + col) = o;
            }
        }
        __syncthreads();  // buffer b free for the next refill
    }
}

extern "C" void kernel_launch(void* const* d_in, const int* in_sizes, int n_in,
                              void* d_out, int out_size) {
    const float* feats  = (const float*)d_in[0];
    const float* scores = (const float*)d_in[1];
    const float* w_reg  = (const float*)d_in[2];
    const float* w_cls  = (const float*)d_in[3];
    const float* b_cls  = (const float*)d_in[4];
    const float* scale  = (const float*)d_in[5];
    const int*   bids   = (const int*)d_in[6];
    const int*   nb     = (n_in > 7) ? (const int*)d_in[7] : nullptr;
    const int*   kp     = (n_in > 8) ? (const int*)d_in[8] : nullptr;
    int N = in_sizes[0] / 256;

    static bool attr_set = false;
    if (!attr_set) {
        cudaFuncSetAttribute(gemv_kernel,
                             cudaFuncAttributeMaxDynamicSharedMemorySize, SMEM_TOT);
        attr_set = true;
    }

    sel_kernel<<<SEL_NCTA, SEL_TPB>>>(scores, bids, b_cls, nb, kp,
                                      (float4*)d_out, N);
    gemv_kernel<<<GE_NCTA, GE_TPB, SMEM_TOT>>>(feats, w_reg, w_cls, b_cls,
                                               scale, (float*)d_out);
}

// round 13
// speedup vs baseline: 1.1127x; 1.1127x over previous
#include <cuda_runtime.h>
#include <cstdint>
#include <math.h>

#define NBIN 65536
#define MAXB 16
#define NMAX 262144
#define ZN (MAXB * NBIN / 4)

#define SEL_TPB 1024
#define SEL_NCTA 296

#define GE_TPB 512
#define GE_NCTA 148
#define TILE_P 96
#define ROWB 1040                    // 260 words: conflict-free x LDS.128
#define XBUF (TILE_P * ROWB)         // 99840
#define SLOT 144                     // 9 x 16B units (odd): conflict-free STS.128
#define SW_OFF (2 * XBUF)            // 199680
#define SIDX_OFF (SW_OFF + 24576)    // 224256
#define SB_OFF (SIDX_OFF + 768)      // 225024
#define MBAR_OFF (SB_OFF + 96)       // 225120
#define SMEM_TOT (MBAR_OFF + 32)     // 225152 (<= 227KB)

// ---- device scratch (zero-init; every run restores zero state) ----
__device__ unsigned g_hist1[MAXB * NBIN];
__device__ unsigned g_hist2[MAXB * NBIN];
__device__ unsigned g_chunk1[MAXB * 256];
__device__ unsigned g_chunk2[MAXB * 256];
__device__ unsigned g_bucket1[MAXB];
__device__ unsigned g_rank1[MAXB];
__device__ unsigned g_kthkey[MAXB];
__device__ int g_list[NMAX];
__device__ int g_cnt;
__device__ unsigned g_bar[8];        // monotonic barrier counters (never reset)

__device__ __forceinline__ unsigned f2key(float s) {
    unsigned u = __float_as_uint(s);
    return (u & 0x80000000u) ? ~u : (u | 0x80000000u);
}
__device__ __forceinline__ unsigned long long ffma2(
    unsigned long long a, unsigned long long b, unsigned long long c) {
    unsigned long long d;
    asm("fma.rn.f32x2 %0, %1, %2, %3;" : "=l"(d) : "l"(a), "l"(b), "l"(c));
    return d;
}
__device__ __forceinline__ unsigned long long addf2(
    unsigned long long a, unsigned long long b) {
    unsigned long long d;
    asm("add.rn.f32x2 %0, %1, %2;" : "=l"(d) : "l"(a), "l"(b));
    return d;
}
__device__ __forceinline__ unsigned long long pack2(float x) {
    unsigned long long d;
    asm("mov.b64 %0, {%1, %1};" : "=l"(d) : "f"(x));
    return d;
}
__device__ __forceinline__ void unpack2(unsigned long long v, float& lo, float& hi) {
    asm("mov.b64 {%0, %1}, %2;" : "=f"(lo), "=f"(hi) : "l"(v));
}
__device__ __forceinline__ float getc(const float4& v, int s) {
    return (s == 0) ? v.x : (s == 1) ? v.y : (s == 2) ? v.z : v.w;
}
__device__ __forceinline__ uint32_t s2u(const void* p) {
    uint32_t a;
    asm("{ .reg .u64 t; cvta.to.shared.u64 t, %1; cvt.u32.u64 %0, t; }"
        : "=r"(a) : "l"(p));
    return a;
}
__device__ __forceinline__ void mbar_init(uint32_t mbar, uint32_t cnt) {
    asm volatile("mbarrier.init.shared.b64 [%0], %1;" :: "r"(mbar), "r"(cnt) : "memory");
}
__device__ __forceinline__ void mbar_expect(uint32_t mbar, uint32_t bytes) {
    asm volatile("mbarrier.arrive.expect_tx.shared.b64 _, [%0], %1;"
                 :: "r"(mbar), "r"(bytes) : "memory");
}
__device__ __forceinline__ void mbar_wait(uint32_t mbar, uint32_t parity) {
    asm volatile(
        "{\n\t.reg .pred P;\n"
        "WL_%=:\n\t"
        "mbarrier.try_wait.parity.acquire.cta.shared::cta.b64 P, [%0], %1, 0x989680;\n\t"
        "@P bra.uni WD_%=;\n\t"
        "bra.uni WL_%=;\n"
        "WD_%=:\n\t}"
        :: "r"(mbar), "r"(parity) : "memory");
}
__device__ __forceinline__ void bulk_copy(uint32_t dst, const void* src,
                                          uint32_t bytes, uint32_t mbar) {
    asm volatile(
        "cp.async.bulk.shared::cluster.global.mbarrier::complete_tx::bytes "
        "[%0], [%1], %2, [%3];"
        :: "r"(dst), "l"(src), "r"(bytes), "r"(mbar) : "memory");
}

// Reset-free grid barrier (SEL_NCTA CTAs, all co-resident).
__device__ __forceinline__ void gbar(int i) {
    __syncthreads();
    if (threadIdx.x == 0) {
        __threadfence();
        unsigned old = atomicAdd(&g_bar[i], 1u);
        unsigned target = old - (old % SEL_NCTA) + SEL_NCTA;
        unsigned cur;
        do {
            asm volatile("ld.acquire.gpu.global.u32 %0, [%1];"
                         : "=r"(cur) : "l"(&g_bar[i]) : "memory");
        } while ((int)(cur - target) < 0);
    }
    __syncthreads();
}

// CTA b handles batch b; threads 0..255 active; two shfl suffix scans.
__device__ void scan_phase(int level, int b, unsigned target,
                           unsigned* wsum, int* s_sel, unsigned* s_rem) {
    const unsigned* h  = (level == 1 ? g_hist1  : g_hist2)  + (size_t)b * NBIN;
    const unsigned* ch = (level == 1 ? g_chunk1 : g_chunk2) + (size_t)b * 256;

    int t = threadIdx.x, lane = t & 31, w = t >> 5;
    unsigned v = 0, x = 0;

    if (t < 256) {
        v = ch[t];
        x = v;
#pragma unroll
        for (int off = 1; off < 32; off <<= 1) {
            unsigned nv = __shfl_down_sync(0xffffffffu, x, off);
            if (lane + off < 32) x += nv;
        }
        if (lane == 0) wsum[w] = x;
    }
    __syncthreads();
    if (t < 256) {
        unsigned add = 0;
        for (int w2 = w + 1; w2 < 8; w2++) add += wsum[w2];
        unsigned s = x + add;
        if (s >= target && s - v < target) { *s_sel = t; *s_rem = target - (s - v); }
    }
    __syncthreads();
    int sel = *s_sel;
    unsigned rem = *s_rem;
    __syncthreads();

    if (t < 256) {
        v = h[sel * 256 + t];
        x = v;
#pragma unroll
        for (int off = 1; off < 32; off <<= 1) {
            unsigned nv = __shfl_down_sync(0xffffffffu, x, off);
            if (lane + off < 32) x += nv;
        }
        if (lane == 0) wsum[w] = x;
    }
    __syncthreads();
    if (t < 256) {
        unsigned add = 0;
        for (int w2 = w + 1; w2 < 8; w2++) add += wsum[w2];
        unsigned s = x + add;
        if (s >= rem && s - v < rem) {
            unsigned bin = (unsigned)(sel * 256 + t);
            if (level == 1) {
                g_bucket1[b] = bin;
                g_rank1[b] = rem - (s - v);
            } else {
                g_kthkey[b] = (g_bucket1[b] << 16) | bin;
            }
        }
    }
}

// Fused selection: hist1 -> scan1 -> hist2 -> scan2 -> compact/fill.
__global__ void __launch_bounds__(SEL_TPB, 2) sel_kernel(
    const float* __restrict__ scores,
    const int* __restrict__ bids,
    const float* __restrict__ b_cls,
    const int* __restrict__ nb_ptr,
    const int* __restrict__ k_ptr,
    float4* __restrict__ out4, int N) {
    __shared__ unsigned wsum[8];
    __shared__ int s_sel;
    __shared__ unsigned s_rem;
    __shared__ float sbq[24];
    __shared__ unsigned skey[MAXB];
    __shared__ int warp_cnt[32];
    __shared__ int warp_off[32];
    __shared__ int cta_base;

    int t = threadIdx.x;
    int bid = blockIdx.x;
    int gid = bid * SEL_TPB + t;

    int B = nb_ptr ? *nb_ptr : 8;
    if (B < 1 || B > MAXB) B = 8;
    unsigned K = (unsigned)(k_ptr ? *k_ptr : 8192);

    // P1: hist1 + chunk1
    if (gid < N) {
        unsigned b = (unsigned)bids[gid];
        if (b < (unsigned)MAXB) {
            unsigned key = f2key(scores[gid]);
            atomicAdd(&g_hist1[b * NBIN + (key >> 16)], 1u);
            atomicAdd(&g_chunk1[b * 256 + (key >> 24)], 1u);
        }
    }
    gbar(0);

    // P2: scan level 1
    if (bid < B) scan_phase(1, bid, K, wsum, &s_sel, &s_rem);
    gbar(1);

    // P3: hist2 + chunk2; zero level-1 state
    if (gid < ZN) reinterpret_cast<uint4*>(g_hist1)[gid] = make_uint4(0u, 0u, 0u, 0u);
    if (gid < MAXB * 256) g_chunk1[gid] = 0u;
    if (gid < N) {
        unsigned b = (unsigned)bids[gid];
        if (b < (unsigned)MAXB) {
            unsigned key = f2key(scores[gid]);
            if ((key >> 16) == g_bucket1[b]) {
                atomicAdd(&g_hist2[b * NBIN + (key & 0xFFFFu)], 1u);
                atomicAdd(&g_chunk2[b * 256 + ((key >> 8) & 0xFFu)], 1u);
            }
        }
    }
    gbar(2);

    // P4: scan level 2 + reset g_cnt
    if (bid == 0 && t == 0) g_cnt = 0;
    if (bid < B) scan_phase(2, bid, g_rank1[bid], wsum, &s_sel, &s_rem);
    gbar(3);

    // P5: compact (CTA-aggregated g_cnt atomic) + fill; zero level-2 state
    if (t < MAXB) skey[t] = g_kthkey[t];
    if (t < 24) sbq[t] = (t < 6) ? 1.0f : b_cls[t - 6];
    __syncthreads();

    if (gid < ZN) reinterpret_cast<uint4*>(g_hist2)[gid] = make_uint4(0u, 0u, 0u, 0u);
    if (gid < MAXB * 256) g_chunk2[gid] = 0u;

    bool keep = false;
    if (gid < N) {
        unsigned b = (unsigned)bids[gid];
        unsigned key = f2key(scores[gid]);
        keep = (b < (unsigned)MAXB) && (key >= skey[b]);
        if (!keep) {
            float4* o = out4 + (size_t)gid * 6;
            o[0] = make_float4(1.f, 1.f, 1.f, 1.f);
            o[1] = make_float4(1.f, 1.f, sbq[6], sbq[7]);
            o[2] = make_float4(sbq[8], sbq[9], sbq[10], sbq[11]);
            o[3] = make_float4(sbq[12], sbq[13], sbq[14], sbq[15]);
            o[4] = make_float4(sbq[16], sbq[17], sbq[18], sbq[19]);
            o[5] = make_float4(sbq[20], sbq[21], sbq[22], sbq[23]);
        }
    }
    int lane = t & 31, w = t >> 5;
    unsigned bal = __ballot_sync(0xffffffffu, keep);
    int nk = __popc(bal);
    if (lane == 0) warp_cnt[w] = nk;
    __syncthreads();
    if (t < 32) {
        int v = warp_cnt[t];
        int inc = v;
#pragma unroll
        for (int o = 1; o < 32; o <<= 1) {
            int n = __shfl_up_sync(0xffffffffu, inc, o);
            if (t >= o) inc += n;
        }
        warp_off[t] = inc - v;
        if (t == 31) cta_base = atomicAdd(&g_cnt, inc);
    }
    __syncthreads();
    if (keep)
        g_list[cta_base + warp_off[w] + __popc(bal & ((1u << lane) - 1u))] = gid;
}

// Staged GEMV: tile=96 pts, 512 thr = 8 k-slices(32k) x 2 output-halves,
// lane owns pts (l, l+32, l+64). Double-buffered cp.async.bulk staging,
// weight prefetch one k ahead, coalesced epilogue stores.
__global__ void __launch_bounds__(GE_TPB, 1) gemv_kernel(
    const float* __restrict__ feats,
    const float* __restrict__ w_reg,
    const float* __restrict__ w_cls,
    const float* __restrict__ b_cls,
    const float* __restrict__ scale,
    float* __restrict__ out) {
    extern __shared__ char smem[];
    float* sw = (float*)(smem + SW_OFF);    // [256][24]
    int* sidx = (int*)(smem + SIDX_OFF);    // [2][96]
    float* sb = (float*)(smem + SB_OFF);
    uint32_t mb0 = s2u(smem + MBAR_OFF);
    uint32_t mb1 = mb0 + 8;

    int t = threadIdx.x;
    int l = t & 31, wid = t >> 5;
    int q = wid & 7;                 // k-slice [32q, 32q+32)
    int jh = wid >> 3;               // output half: floats [12jh, 12jh+12)

    if (t < 24) sb[t] = (t < 6) ? 1.0f : b_cls[t - 6];
    for (int i = t; i < 6144; i += GE_TPB) {
        int k = i / 24, j = i % 24;
        sw[i] = (j < 6) ? w_reg[k * 6 + j] : w_cls[k * 18 + (j - 6)];
    }
    if (t < 2) mbar_init(t == 0 ? mb0 : mb1, 1);
    float sc = scale[0];
    int T = g_cnt;
    int ntiles = (T + TILE_P - 1) / TILE_P;
    __syncthreads();

    int tile = blockIdx.x;
    int ph0 = 0, ph1 = 0;

    if (tile < ntiles) {
        int nv = min(TILE_P, T - tile * TILE_P);
        if (t < TILE_P) sidx[t] = (t < nv) ? g_list[tile * TILE_P + t] : 0;
        if (t == 0) mbar_expect(mb0, (unsigned)nv << 10);
    }
    __syncthreads();
    if (tile < ntiles && t < min(TILE_P, T - tile * TILE_P))
        bulk_copy(s2u(smem) + t * ROWB, feats + (size_t)sidx[t] * 256, 1024, mb0);

    // per-(q,jh) weight base: k-stride = 96B = 6 ulonglong2
    const ulonglong2* wp = (const ulonglong2*)(sw + q * 768 + jh * 12);

    int b = 0;
    for (; tile < ntiles; tile += GE_NCTA, b ^= 1) {
        int nv = min(TILE_P, T - tile * TILE_P);
        int nxt = tile + GE_NCTA;
        int bn = b ^ 1;
        uint32_t mbn = bn ? mb1 : mb0;

        if (nxt < ntiles) {
            int nv2 = min(TILE_P, T - nxt * TILE_P);
            if (t < TILE_P) sidx[bn * TILE_P + t] = (t < nv2) ? g_list[nxt * TILE_P + t] : 0;
            if (t == 0) mbar_expect(mbn, (unsigned)nv2 << 10);
        }
        __syncthreads();
        if (nxt < ntiles) {
            int nv2 = min(TILE_P, T - nxt * TILE_P);
            if (t < nv2)
                bulk_copy(s2u(smem) + bn * XBUF + t * ROWB,
                          feats + (size_t)sidx[bn * TILE_P + t] * 256, 1024, mbn);
        }

        if (b == 0) { mbar_wait(mb0, ph0); ph0 ^= 1; }
        else        { mbar_wait(mb1, ph1); ph1 ^= 1; }

        // compute: pts (l, l+32, l+64), k in [32q,32q+32), pairs [6jh,6jh+6)
        const float4* x0 = (const float4*)(smem + b * XBUF + l * ROWB) + q * 8;
        const float4* x1 = x0 + 32 * 65;   // +32 rows (65 float4 per row)
        const float4* x2 = x0 + 64 * 65;
        unsigned long long acc0[6], acc1[6], acc2[6];
#pragma unroll
        for (int j = 0; j < 6; j++) { acc0[j] = 0ull; acc1[j] = 0ull; acc2[j] = 0ull; }

        ulonglong2 wA0 = wp[0], wA1 = wp[1], wA2 = wp[2];  // k = 32q
        float4 a0 = x0[0], a1 = x1[0], a2 = x2[0];
#pragma unroll
        for (int c4 = 0; c4 < 8; c4++) {
            float4 n0, n1, n2;
            if (c4 < 7) { n0 = x0[c4 + 1]; n1 = x1[c4 + 1]; n2 = x2[c4 + 1]; }
#pragma unroll
            for (int s = 0; s < 4; s++) {
                ulonglong2 w0 = wA0, w1 = wA1, w2 = wA2;
                int kn = c4 * 4 + s + 1;
                if (kn < 32) {
                    const ulonglong2* wn = wp + kn * 6;
                    wA0 = wn[0]; wA1 = wn[1]; wA2 = wn[2];
                }
                unsigned long long xx0 = pack2(getc(a0, s));
                unsigned long long xx1 = pack2(getc(a1, s));
                unsigned long long xx2 = pack2(getc(a2, s));
                acc0[0] = ffma2(xx0, w0.x, acc0[0]);
                acc0[1] = ffma2(xx0, w0.y, acc0[1]);
                acc0[2] = ffma2(xx0, w1.x, acc0[2]);
                acc0[3] = ffma2(xx0, w1.y, acc0[3]);
                acc0[4] = ffma2(xx0, w2.x, acc0[4]);
                acc0[5] = ffma2(xx0, w2.y, acc0[5]);
                acc1[0] = ffma2(xx1, w0.x, acc1[0]);
                acc1[1] = ffma2(xx1, w0.y, acc1[1]);
                acc1[2] = ffma2(xx1, w1.x, acc1[2]);
                acc1[3] = ffma2(xx1, w1.y, acc1[3]);
                acc1[4] = ffma2(xx1, w2.x, acc1[4]);
                acc1[5] = ffma2(xx1, w2.y, acc1[5]);
                acc2[0] = ffma2(xx2, w0.x, acc2[0]);
                acc2[1] = ffma2(xx2, w0.y, acc2[1]);
                acc2[2] = ffma2(xx2, w1.x, acc2[2]);
                acc2[3] = ffma2(xx2, w1.y, acc2[3]);
                acc2[4] = ffma2(xx2, w2.x, acc2[4]);
                acc2[5] = ffma2(xx2, w2.y, acc2[5]);
            }
            a0 = n0; a1 = n1; a2 = n2;
        }
        __syncthreads();  // all x reads done; buffer b becomes scratch

        // fold store: slot (wid*32+l) = (q,jh,l); 9 x STS.128
        // 512 slots x 144 B = 73728 <= XBUF; stride 9x16B (odd): conflict-free
        char* scratch = smem + b * XBUF;
        {
            ulonglong2* dst = (ulonglong2*)(scratch + (wid * 32 + l) * SLOT);
            dst[0] = make_ulonglong2(acc0[0], acc0[1]);
            dst[1] = make_ulonglong2(acc0[2], acc0[3]);
            dst[2] = make_ulonglong2(acc0[4], acc0[5]);
            dst[3] = make_ulonglong2(acc1[0], acc1[1]);
            dst[4] = make_ulonglong2(acc1[2], acc1[3]);
            dst[5] = make_ulonglong2(acc1[4], acc1[5]);
            dst[6] = make_ulonglong2(acc2[0], acc2[1]);
            dst[7] = make_ulonglong2(acc2[2], acc2[3]);
            dst[8] = make_ulonglong2(acc2[4], acc2[5]);
        }
        __syncthreads();

        // epilogue: fold 8 q-partials; jj fastest -> coalesced output rows
        for (int s = t; s < TILE_P * 12; s += GE_TPB) {
            int pt = s / 12, jj = s % 12;       // jj in [0,12)
            int jh2 = jj / 6, j6 = jj % 6;
            int psub = pt >> 5, pl = pt & 31;
            unsigned long long sum = 0ull;
#pragma unroll
            for (int q2 = 0; q2 < 8; q2++) {
                unsigned long long pv = *(const unsigned long long*)(
                    scratch + ((jh2 * 8 + q2) * 32 + pl) * SLOT + psub * 48 + j6 * 8);
                sum = addf2(sum, pv);
            }
            if (pt < nv) {
                float lo, hi;
                unpack2(sum, lo, hi);
                int col = jj << 1;
                float2 o;
                if (col < 6) { o.x = __expf(sc * lo); o.y = __expf(sc * hi); }
                else         { o.x = lo + sb[col];    o.y = hi + sb[col + 1]; }
                *(float2*)(out + (size_t)sidx[b * TILE_P + pt] * 24 + col) = o;
            }
        }
        __syncthreads();  // buffer b free for the next refill
    }
}

extern "C" void kernel_launch(void* const* d_in, const int* in_sizes, int n_in,
                              void* d_out, int out_size) {
    const float* feats  = (const float*)d_in[0];
    const float* scores = (const float*)d_in[1];
    const float* w_reg  = (const float*)d_in[2];
    const float* w_cls  = (const float*)d_in[3];
    const float* b_cls  = (const float*)d_in[4];
    const float* scale  = (const float*)d_in[5];
    const int*   bids   = (const int*)d_in[6];
    const int*   nb     = (n_in > 7) ? (const int*)d_in[7] : nullptr;
    const int*   kp     = (n_in > 8) ? (const int*)d_in[8] : nullptr;
    int N = in_sizes[0] / 256;

    static bool attr_set = false;
    if (!attr_set) {
        cudaFuncSetAttribute(gemv_kernel,
                             cudaFuncAttributeMaxDynamicSharedMemorySize, SMEM_TOT);
        attr_set = true;
    }

    sel_kernel<<<SEL_NCTA, SEL_TPB>>>(scores, bids, b_cls, nb, kp,
                                      (float4*)d_out, N);
    gemv_kernel<<<GE_NCTA, GE_TPB, SMEM_TOT>>>(feats, w_reg, w_cls, b_cls,
                                               scale, (float*)d_out);
}

// round 14
// speedup vs baseline: 1.1504x; 1.0338x over previous
#include <cuda_runtime.h>
#include <cstdint>
#include <math.h>

#define NBIN 65536
#define MAXB 16
#define NMAX 262144
#define ZN (MAXB * NBIN / 4)

#define SEL_TPB 1024
#define SEL_NCTA 296

#define GE_TPB 512
#define GE_NCTA 296                  // 2 CTAs per SM
#define TILE_P 64
#define ROWB 1040                    // 260 words: conflict-free x LDS.128
#define XBUF (TILE_P * ROWB)         // 66560 (single buffer)
#define SLOT 112                     // 28 words: conflict-free fold STS.128
#define SW_OFF XBUF                  // 66560
#define SIDX_OFF (SW_OFF + 24576)    // 91136
#define SB_OFF (SIDX_OFF + 256)     // 91392
#define MBAR_OFF (SB_OFF + 96)       // 91488
#define SMEM_TOT (MBAR_OFF + 32)     // 91520 -> 2 CTAs/SM

// ---- device scratch (zero-init; every run restores zero state) ----
__device__ unsigned g_hist1[MAXB * NBIN];
__device__ unsigned g_hist2[MAXB * NBIN];
__device__ unsigned g_chunk1[MAXB * 256];
__device__ unsigned g_chunk2[MAXB * 256];
__device__ unsigned g_bucket1[MAXB];
__device__ unsigned g_rank1[MAXB];
__device__ unsigned g_kthkey[MAXB];
__device__ int g_list[NMAX];
__device__ int g_cnt;
__device__ unsigned g_bar[8];        // monotonic barrier counters (never reset)

__device__ __forceinline__ unsigned f2key(float s) {
    unsigned u = __float_as_uint(s);
    return (u & 0x80000000u) ? ~u : (u | 0x80000000u);
}
__device__ __forceinline__ unsigned long long ffma2(
    unsigned long long a, unsigned long long b, unsigned long long c) {
    unsigned long long d;
    asm("fma.rn.f32x2 %0, %1, %2, %3;" : "=l"(d) : "l"(a), "l"(b), "l"(c));
    return d;
}
__device__ __forceinline__ unsigned long long addf2(
    unsigned long long a, unsigned long long b) {
    unsigned long long d;
    asm("add.rn.f32x2 %0, %1, %2;" : "=l"(d) : "l"(a), "l"(b));
    return d;
}
__device__ __forceinline__ unsigned long long pack2(float x) {
    unsigned long long d;
    asm("mov.b64 %0, {%1, %1};" : "=l"(d) : "f"(x));
    return d;
}
__device__ __forceinline__ void unpack2(unsigned long long v, float& lo, float& hi) {
    asm("mov.b64 {%0, %1}, %2;" : "=f"(lo), "=f"(hi) : "l"(v));
}
__device__ __forceinline__ float getc(const float4& v, int s) {
    return (s == 0) ? v.x : (s == 1) ? v.y : (s == 2) ? v.z : v.w;
}
__device__ __forceinline__ uint32_t s2u(const void* p) {
    uint32_t a;
    asm("{ .reg .u64 t; cvta.to.shared.u64 t, %1; cvt.u32.u64 %0, t; }"
        : "=r"(a) : "l"(p));
    return a;
}
__device__ __forceinline__ void mbar_init(uint32_t mbar, uint32_t cnt) {
    asm volatile("mbarrier.init.shared.b64 [%0], %1;" :: "r"(mbar), "r"(cnt) : "memory");
}
__device__ __forceinline__ void mbar_expect(uint32_t mbar, uint32_t bytes) {
    asm volatile("mbarrier.arrive.expect_tx.shared.b64 _, [%0], %1;"
                 :: "r"(mbar), "r"(bytes) : "memory");
}
__device__ __forceinline__ void mbar_wait(uint32_t mbar, uint32_t parity) {
    asm volatile(
        "{\n\t.reg .pred P;\n"
        "WL_%=:\n\t"
        "mbarrier.try_wait.parity.acquire.cta.shared::cta.b64 P, [%0], %1, 0x989680;\n\t"
        "@P bra.uni WD_%=;\n\t"
        "bra.uni WL_%=;\n"
        "WD_%=:\n\t}"
        :: "r"(mbar), "r"(parity) : "memory");
}
__device__ __forceinline__ void bulk_copy(uint32_t dst, const void* src,
                                          uint32_t bytes, uint32_t mbar) {
    asm volatile(
        "cp.async.bulk.shared::cluster.global.mbarrier::complete_tx::bytes "
        "[%0], [%1], %2, [%3];"
        :: "r"(dst), "l"(src), "r"(bytes), "r"(mbar) : "memory");
}

// Reset-free grid barrier (SEL_NCTA CTAs, all co-resident).
__device__ __forceinline__ void gbar(int i) {
    __syncthreads();
    if (threadIdx.x == 0) {
        __threadfence();
        unsigned old = atomicAdd(&g_bar[i], 1u);
        unsigned target = old - (old % SEL_NCTA) + SEL_NCTA;
        unsigned cur;
        do {
            asm volatile("ld.acquire.gpu.global.u32 %0, [%1];"
                         : "=r"(cur) : "l"(&g_bar[i]) : "memory");
        } while ((int)(cur - target) < 0);
    }
    __syncthreads();
}

// CTA b handles batch b; threads 0..255 active; two shfl suffix scans.
__device__ void scan_phase(int level, int b, unsigned target,
                           unsigned* wsum, int* s_sel, unsigned* s_rem) {
    const unsigned* h  = (level == 1 ? g_hist1  : g_hist2)  + (size_t)b * NBIN;
    const unsigned* ch = (level == 1 ? g_chunk1 : g_chunk2) + (size_t)b * 256;

    int t = threadIdx.x, lane = t & 31, w = t >> 5;
    unsigned v = 0, x = 0;

    if (t < 256) {
        v = ch[t];
        x = v;
#pragma unroll
        for (int off = 1; off < 32; off <<= 1) {
            unsigned nv = __shfl_down_sync(0xffffffffu, x, off);
            if (lane + off < 32) x += nv;
        }
        if (lane == 0) wsum[w] = x;
    }
    __syncthreads();
    if (t < 256) {
        unsigned add = 0;
        for (int w2 = w + 1; w2 < 8; w2++) add += wsum[w2];
        unsigned s = x + add;
        if (s >= target && s - v < target) { *s_sel = t; *s_rem = target - (s - v); }
    }
    __syncthreads();
    int sel = *s_sel;
    unsigned rem = *s_rem;
    __syncthreads();

    if (t < 256) {
        v = h[sel * 256 + t];
        x = v;
#pragma unroll
        for (int off = 1; off < 32; off <<= 1) {
            unsigned nv = __shfl_down_sync(0xffffffffu, x, off);
            if (lane + off < 32) x += nv;
        }
        if (lane == 0) wsum[w] = x;
    }
    __syncthreads();
    if (t < 256) {
        unsigned add = 0;
        for (int w2 = w + 1; w2 < 8; w2++) add += wsum[w2];
        unsigned s = x + add;
        if (s >= rem && s - v < rem) {
            unsigned bin = (unsigned)(sel * 256 + t);
            if (level == 1) {
                g_bucket1[b] = bin;
                g_rank1[b] = rem - (s - v);
            } else {
                g_kthkey[b] = (g_bucket1[b] << 16) | bin;
            }
        }
    }
}

// Fused selection: hist1 -> scan1 -> hist2 -> scan2 -> compact/fill.
__global__ void __launch_bounds__(SEL_TPB, 2) sel_kernel(
    const float* __restrict__ scores,
    const int* __restrict__ bids,
    const float* __restrict__ b_cls,
    const int* __restrict__ nb_ptr,
    const int* __restrict__ k_ptr,
    float4* __restrict__ out4, int N) {
    __shared__ unsigned wsum[8];
    __shared__ int s_sel;
    __shared__ unsigned s_rem;
    __shared__ float sbq[24];
    __shared__ unsigned skey[MAXB];
    __shared__ int warp_cnt[32];
    __shared__ int warp_off[32];
    __shared__ int cta_base;

    int t = threadIdx.x;
    int bid = blockIdx.x;
    int gid = bid * SEL_TPB + t;

    int B = nb_ptr ? *nb_ptr : 8;
    if (B < 1 || B > MAXB) B = 8;
    unsigned K = (unsigned)(k_ptr ? *k_ptr : 8192);

    // P1: hist1 + chunk1
    if (gid < N) {
        unsigned b = (unsigned)bids[gid];
        if (b < (unsigned)MAXB) {
            unsigned key = f2key(scores[gid]);
            atomicAdd(&g_hist1[b * NBIN + (key >> 16)], 1u);
            atomicAdd(&g_chunk1[b * 256 + (key >> 24)], 1u);
        }
    }
    gbar(0);

    // P2: scan level 1
    if (bid < B) scan_phase(1, bid, K, wsum, &s_sel, &s_rem);
    gbar(1);

    // P3: hist2 + chunk2; zero level-1 state
    if (gid < ZN) reinterpret_cast<uint4*>(g_hist1)[gid] = make_uint4(0u, 0u, 0u, 0u);
    if (gid < MAXB * 256) g_chunk1[gid] = 0u;
    if (gid < N) {
        unsigned b = (unsigned)bids[gid];
        if (b < (unsigned)MAXB) {
            unsigned key = f2key(scores[gid]);
            if ((key >> 16) == g_bucket1[b]) {
                atomicAdd(&g_hist2[b * NBIN + (key & 0xFFFFu)], 1u);
                atomicAdd(&g_chunk2[b * 256 + ((key >> 8) & 0xFFu)], 1u);
            }
        }
    }
    gbar(2);

    // P4: scan level 2 + reset g_cnt
    if (bid == 0 && t == 0) g_cnt = 0;
    if (bid < B) scan_phase(2, bid, g_rank1[bid], wsum, &s_sel, &s_rem);
    gbar(3);

    // P5: compact (CTA-aggregated g_cnt atomic) + fill; zero level-2 state
    if (t < MAXB) skey[t] = g_kthkey[t];
    if (t < 24) sbq[t] = (t < 6) ? 1.0f : b_cls[t - 6];
    __syncthreads();

    if (gid < ZN) reinterpret_cast<uint4*>(g_hist2)[gid] = make_uint4(0u, 0u, 0u, 0u);
    if (gid < MAXB * 256) g_chunk2[gid] = 0u;

    bool keep = false;
    if (gid < N) {
        unsigned b = (unsigned)bids[gid];
        unsigned key = f2key(scores[gid]);
        keep = (b < (unsigned)MAXB) && (key >= skey[b]);
        if (!keep) {
            float4* o = out4 + (size_t)gid * 6;
            o[0] = make_float4(1.f, 1.f, 1.f, 1.f);
            o[1] = make_float4(1.f, 1.f, sbq[6], sbq[7]);
            o[2] = make_float4(sbq[8], sbq[9], sbq[10], sbq[11]);
            o[3] = make_float4(sbq[12], sbq[13], sbq[14], sbq[15]);
            o[4] = make_float4(sbq[16], sbq[17], sbq[18], sbq[19]);
            o[5] = make_float4(sbq[20], sbq[21], sbq[22], sbq[23]);
        }
    }
    int lane = t & 31, w = t >> 5;
    unsigned bal = __ballot_sync(0xffffffffu, keep);
    int nk = __popc(bal);
    if (lane == 0) warp_cnt[w] = nk;
    __syncthreads();
    if (t < 32) {
        int v = warp_cnt[t];
        int inc = v;
#pragma unroll
        for (int o = 1; o < 32; o <<= 1) {
            int n = __shfl_up_sync(0xffffffffu, inc, o);
            if (t >= o) inc += n;
        }
        warp_off[t] = inc - v;
        if (t == 31) cta_base = atomicAdd(&g_cnt, inc);
    }
    __syncthreads();
    if (keep)
        g_list[cta_base + warp_off[w] + __popc(bal & ((1u << lane) - 1u))] = gid;
}

// Staged GEMV: tile=64 pts, 512 thr = 8 k-slices(32k) x 2 output-halves,
// lane owns pts (l, l+32). Single x-buffer; 2 CTAs/SM provide copy/compute
// overlap across CTAs (8 warps/SMSP hide LDS latency).
__global__ void __launch_bounds__(GE_TPB, 2) gemv_kernel(
    const float* __restrict__ feats,
    const float* __restrict__ w_reg,
    const float* __restrict__ w_cls,
    const float* __restrict__ b_cls,
    const float* __restrict__ scale,
    float* __restrict__ out) {
    extern __shared__ char smem[];
    float* sw = (float*)(smem + SW_OFF);    // [256][24]
    int* sidx = (int*)(smem + SIDX_OFF);    // [64]
    float* sb = (float*)(smem + SB_OFF);
    uint32_t mb0 = s2u(smem + MBAR_OFF);

    int t = threadIdx.x;
    int l = t & 31, wid = t >> 5;
    int q = wid & 7;                 // k-slice [32q, 32q+32)
    int jh = wid >> 3;               // output half: floats [12jh, 12jh+12)

    if (t < 24) sb[t] = (t < 6) ? 1.0f : b_cls[t - 6];
    for (int i = t; i < 6144; i += GE_TPB) {
        int k = i / 24, j = i % 24;
        sw[i] = (j < 6) ? w_reg[k * 6 + j] : w_cls[k * 18 + (j - 6)];
    }
    if (t == 0) mbar_init(mb0, 1);
    float sc = scale[0];
    int T = g_cnt;
    int ntiles = (T + TILE_P - 1) / TILE_P;
    __syncthreads();

    int tile = blockIdx.x;
    int ph = 0;

    // prologue: stage indices + issue copies for the first tile
    if (tile < ntiles) {
        int nv = min(TILE_P, T - tile * TILE_P);
        if (t < TILE_P) sidx[t] = (t < nv) ? g_list[tile * TILE_P + t] : 0;
        if (t == 0) mbar_expect(mb0, (unsigned)nv << 10);
    }
    __syncthreads();
    if (tile < ntiles && t < min(TILE_P, T - tile * TILE_P))
        bulk_copy(s2u(smem) + t * ROWB, feats + (size_t)sidx[t] * 256, 1024, mb0);

    // per-(q,jh) weight base: k-stride = 96B = 6 ulonglong2
    const ulonglong2* wp = (const ulonglong2*)(sw + q * 768 + jh * 12);

    for (; tile < ntiles; tile += GE_NCTA) {
        int nv = min(TILE_P, T - tile * TILE_P);

        mbar_wait(mb0, ph);
        ph ^= 1;

        // compute: pts (l, l+32), k in [32q,32q+32), output pairs [6jh,6jh+6)
        const float4* x0 = (const float4*)(smem + l * ROWB) + q * 8;
        const float4* x1 = x0 + 32 * 65;   // +32 rows (65 float4 per row)
        unsigned long long acc0[6], acc1[6];
#pragma unroll
        for (int j = 0; j < 6; j++) { acc0[j] = 0ull; acc1[j] = 0ull; }

#pragma unroll
        for (int c4 = 0; c4 < 8; c4++) {
            float4 a0 = x0[c4];
            float4 a1 = x1[c4];
#pragma unroll
            for (int s = 0; s < 4; s++) {
                const ulonglong2* wn = wp + (c4 * 4 + s) * 6;
                ulonglong2 w0 = wn[0], w1 = wn[1], w2 = wn[2];
                unsigned long long xx0 = pack2(getc(a0, s));
                unsigned long long xx1 = pack2(getc(a1, s));
                acc0[0] = ffma2(xx0, w0.x, acc0[0]);
                acc0[1] = ffma2(xx0, w0.y, acc0[1]);
                acc0[2] = ffma2(xx0, w1.x, acc0[2]);
                acc0[3] = ffma2(xx0, w1.y, acc0[3]);
                acc0[4] = ffma2(xx0, w2.x, acc0[4]);
                acc0[5] = ffma2(xx0, w2.y, acc0[5]);
                acc1[0] = ffma2(xx1, w0.x, acc1[0]);
                acc1[1] = ffma2(xx1, w0.y, acc1[1]);
                acc1[2] = ffma2(xx1, w1.x, acc1[2]);
                acc1[3] = ffma2(xx1, w1.y, acc1[3]);
                acc1[4] = ffma2(xx1, w2.x, acc1[4]);
                acc1[5] = ffma2(xx1, w2.y, acc1[5]);
            }
        }
        __syncthreads();  // all x reads done; x buffer becomes scratch

        // single-phase fold store: slot (wid*32+l), 6 x STS.128
        // 512 slots x 112 B = 57344 <= XBUF; 28-word stride: conflict-free
        char* scratch = smem;
        {
            ulonglong2* dst = (ulonglong2*)(scratch + (wid * 32 + l) * SLOT);
            dst[0] = make_ulonglong2(acc0[0], acc0[1]);
            dst[1] = make_ulonglong2(acc0[2], acc0[3]);
            dst[2] = make_ulonglong2(acc0[4], acc0[5]);
            dst[3] = make_ulonglong2(acc1[0], acc1[1]);
            dst[4] = make_ulonglong2(acc1[2], acc1[3]);
            dst[5] = make_ulonglong2(acc1[4], acc1[5]);
        }
        __syncthreads();

        // epilogue: fold 8 q-partials; jj fastest -> coalesced output rows
        for (int s = t; s < TILE_P * 12; s += GE_TPB) {
            int pt = s / 12, jj = s % 12;       // jj in [0,12)
            int jh2 = jj / 6, j6 = jj % 6;
            int psub = pt >> 5, pl = pt & 31;
            unsigned long long sum = 0ull;
#pragma unroll
            for (int q2 = 0; q2 < 8; q2++) {
                unsigned long long pv = *(const unsigned long long*)(
                    scratch + ((jh2 * 8 + q2) * 32 + pl) * SLOT + psub * 48 + j6 * 8);
                sum = addf2(sum, pv);
            }
            if (pt < nv) {
                float lo, hi;
                unpack2(sum, lo, hi);
                int col = jj << 1;
                float2 o;
                if (col < 6) { o.x = __expf(sc * lo); o.y = __expf(sc * hi); }
                else         { o.x = lo + sb[col];    o.y = hi + sb[col + 1]; }
                *(float2*)(out + (size_t)sidx[pt] * 24 + col) = o;
            }
        }
        __syncthreads();  // scratch + sidx reads done

        // stage next tile: indices + copies into the (now free) x buffer
        int nxt = tile + GE_NCTA;
        if (nxt < ntiles) {
            int nv2 = min(TILE_P, T - nxt * TILE_P);
            if (t < TILE_P) sidx[t] = (t < nv2) ? g_list[nxt * TILE_P + t] : 0;
            if (t == 0) mbar_expect(mb0, (unsigned)nv2 << 10);
        }
        __syncthreads();
        if (nxt < ntiles) {
            int nv2 = min(TILE_P, T - nxt * TILE_P);
            if (t < nv2)
                bulk_copy(s2u(smem) + t * ROWB,
                          feats + (size_t)sidx[t] * 256, 1024, mb0);
        }
    }
}

extern "C" void kernel_launch(void* const* d_in, const int* in_sizes, int n_in,
                              void* d_out, int out_size) {
    const float* feats  = (const float*)d_in[0];
    const float* scores = (const float*)d_in[1];
    const float* w_reg  = (const float*)d_in[2];
    const float* w_cls  = (const float*)d_in[3];
    const float* b_cls  = (const float*)d_in[4];
    const float* scale  = (const float*)d_in[5];
    const int*   bids   = (const int*)d_in[6];
    const int*   nb     = (n_in > 7) ? (const int*)d_in[7] : nullptr;
    const int*   kp     = (n_in > 8) ? (const int*)d_in[8] : nullptr;
    int N = in_sizes[0] / 256;

    static bool attr_set = false;
    if (!attr_set) {
        cudaFuncSetAttribute(gemv_kernel,
                             cudaFuncAttributeMaxDynamicSharedMemorySize, SMEM_TOT);
        attr_set = true;
    }

    sel_kernel<<<SEL_NCTA, SEL_TPB>>>(scores, bids, b_cls, nb, kp,
                                      (float4*)d_out, N);
    gemv_kernel<<<GE_NCTA, GE_TPB, SMEM_TOT>>>(feats, w_reg, w_cls, b_cls,
                                               scale, (float*)d_out);
}